// round 2
// baseline (speedup 1.0000x reference)
#include <cuda_runtime.h>
#include <cstdint>

#define BATCH 2
#define SEQ   2048
#define NHEAD 16
#define HDIM  64
#define EDIM  1024

// Scratch (static device globals: allocation-free per harness rules)
__device__ float g_q[(size_t)BATCH * NHEAD * SEQ * HDIM];
__device__ float g_k[(size_t)BATCH * NHEAD * SEQ * HDIM];
__device__ float g_v[(size_t)BATCH * NHEAD * SEQ * HDIM];
__device__ float g_att[(size_t)BATCH * SEQ * EDIM];

__device__ __forceinline__ uint32_t f2tf(float f) {
    uint32_t u;
    asm("cvt.rna.tf32.f32 %0, %1;" : "=r"(u) : "f"(f));
    return u;
}

__device__ __forceinline__ void mma_tf32(float* c, const uint32_t* a, const uint32_t* b) {
    asm volatile(
        "mma.sync.aligned.m16n8k8.row.col.f32.tf32.tf32.f32 "
        "{%0,%1,%2,%3}, {%4,%5,%6,%7}, {%8,%9}, {%0,%1,%2,%3};"
        : "+f"(c[0]), "+f"(c[1]), "+f"(c[2]), "+f"(c[3])
        : "r"(a[0]), "r"(a[1]), "r"(a[2]), "r"(a[3]), "r"(b[0]), "r"(b[1]));
}

// Scatter one QKV output element with bias + head_mask into [B,H,S,hd] buffers.
__device__ __forceinline__ void store_qkv_elem(int r, int e, float v,
                                               const float* bias, const float* mask) {
    int bb  = r >> 11;            // batch (S=2048)
    int s   = r & (SEQ - 1);
    int h   = e / 192;            // 3*hd = 192 per head
    int rem = e - h * 192;
    int which = rem >> 6;         // 0=q, 1=k, 2=v
    int j   = rem & 63;
    float val = (v + bias[e]) * mask[h];
    float* basep = (which == 0) ? g_q : (which == 1) ? g_k : g_v;
    basep[(((size_t)(bb * NHEAD + h)) * SEQ + s) * HDIM + j] = val;
}

// ---------------------------------------------------------------------------
// Generic tf32 GEMM: C[M,N] = A[M,K] @ W[N,K]^T  (both K-major => mma row.col)
// MODE 0: FC epilogue  (out = C + bias, row-major [M,N]), A is g_att
// MODE 1: QKV epilogue (scatter with bias + head_mask), A is param
// Tiles: BM=BN=128, BK=32; 256 threads; warp grid 4x2, warp tile 32x64.
// ---------------------------------------------------------------------------
template <int MODE>
__global__ __launch_bounds__(256)
void gemm_tf32_kernel(const float* __restrict__ A,
                      const float* __restrict__ W,
                      const float* __restrict__ bias,
                      const float* __restrict__ mask,
                      float* __restrict__ out,
                      int M, int N, int K)
{
    __shared__ float sA[128][36];   // +4 pad -> conflict-free frag loads
    __shared__ float sB[128][36];

    const int tid  = threadIdx.x;
    const int warp = tid >> 5;
    const int lane = tid & 31;
    const int g    = lane >> 2;   // groupID (0..7)
    const int t    = lane & 3;    // thread-in-group (0..3)
    const int wm   = warp >> 1;   // 0..3
    const int wn   = warp & 1;    // 0..1
    const int m0   = blockIdx.y * 128;
    const int n0   = blockIdx.x * 128;

    const float* Ap = (MODE == 0) ? (const float*)g_att : A;

    float acc[2][8][4];
    #pragma unroll
    for (int mi = 0; mi < 2; mi++)
        #pragma unroll
        for (int ni = 0; ni < 8; ni++)
            #pragma unroll
            for (int j = 0; j < 4; j++) acc[mi][ni][j] = 0.0f;

    const int lrow = tid >> 3;        // 0..31
    const int lcol = (tid & 7) << 2;  // 0,4,...,28

    for (int k0 = 0; k0 < K; k0 += 32) {
        __syncthreads();
        #pragma unroll
        for (int i = 0; i < 4; i++) {
            int r = lrow + i * 32;
            float4 va = *(const float4*)(Ap + (size_t)(m0 + r) * K + k0 + lcol);
            float4 vb = *(const float4*)(W  + (size_t)(n0 + r) * K + k0 + lcol);
            sA[r][lcol + 0] = __uint_as_float(f2tf(va.x));
            sA[r][lcol + 1] = __uint_as_float(f2tf(va.y));
            sA[r][lcol + 2] = __uint_as_float(f2tf(va.z));
            sA[r][lcol + 3] = __uint_as_float(f2tf(va.w));
            sB[r][lcol + 0] = __uint_as_float(f2tf(vb.x));
            sB[r][lcol + 1] = __uint_as_float(f2tf(vb.y));
            sB[r][lcol + 2] = __uint_as_float(f2tf(vb.z));
            sB[r][lcol + 3] = __uint_as_float(f2tf(vb.w));
        }
        __syncthreads();

        #pragma unroll
        for (int kk = 0; kk < 4; kk++) {
            uint32_t a[2][4];
            uint32_t bb[8][2];
            #pragma unroll
            for (int mi = 0; mi < 2; mi++) {
                int r = wm * 32 + mi * 16 + g;
                a[mi][0] = __float_as_uint(sA[r    ][kk * 8 + t]);
                a[mi][1] = __float_as_uint(sA[r + 8][kk * 8 + t]);
                a[mi][2] = __float_as_uint(sA[r    ][kk * 8 + t + 4]);
                a[mi][3] = __float_as_uint(sA[r + 8][kk * 8 + t + 4]);
            }
            #pragma unroll
            for (int ni = 0; ni < 8; ni++) {
                int rn = wn * 64 + ni * 8 + g;
                bb[ni][0] = __float_as_uint(sB[rn][kk * 8 + t]);
                bb[ni][1] = __float_as_uint(sB[rn][kk * 8 + t + 4]);
            }
            #pragma unroll
            for (int mi = 0; mi < 2; mi++)
                #pragma unroll
                for (int ni = 0; ni < 8; ni++)
                    mma_tf32(acc[mi][ni], a[mi], bb[ni]);
        }
    }

    // Epilogue
    #pragma unroll
    for (int mi = 0; mi < 2; mi++) {
        #pragma unroll
        for (int ni = 0; ni < 8; ni++) {
            int r0 = m0 + wm * 32 + mi * 16 + g;
            int cc = n0 + wn * 64 + ni * 8 + 2 * t;
            if (MODE == 0) {
                float b0 = bias[cc], b1 = bias[cc + 1];
                out[(size_t)r0 * N + cc]           = acc[mi][ni][0] + b0;
                out[(size_t)r0 * N + cc + 1]       = acc[mi][ni][1] + b1;
                out[(size_t)(r0 + 8) * N + cc]     = acc[mi][ni][2] + b0;
                out[(size_t)(r0 + 8) * N + cc + 1] = acc[mi][ni][3] + b1;
            } else {
                store_qkv_elem(r0,     cc,     acc[mi][ni][0], bias, mask);
                store_qkv_elem(r0,     cc + 1, acc[mi][ni][1], bias, mask);
                store_qkv_elem(r0 + 8, cc,     acc[mi][ni][2], bias, mask);
                store_qkv_elem(r0 + 8, cc + 1, acc[mi][ni][3], bias, mask);
            }
        }
    }
}

// ---------------------------------------------------------------------------
// Flash attention: one CTA = (batch b, head h, 64-row Q tile). 128 threads.
// Smem: sQ (reused as P) / sK / sV, each 64 x 72 f32 (pad 8 -> conflict-free).
// QK^T and P@V via tf32 mma; online softmax in fp32 registers.
// ---------------------------------------------------------------------------
__global__ __launch_bounds__(128)
void flash_attn_kernel()
{
    extern __shared__ float sm[];
    float* sQ = sm;                 // 64 x 72, reused as P after frag extraction
    float* sK = sm + 64 * 72;
    float* sV = sm + 2 * 64 * 72;

    const int tid  = threadIdx.x;
    const int warp = tid >> 5;
    const int lane = tid & 31;
    const int g    = lane >> 2;
    const int t    = lane & 3;
    const int qt = blockIdx.x;
    const int h  = blockIdx.y;
    const int b  = blockIdx.z;

    const size_t base = ((size_t)(b * NHEAD + h)) * SEQ * HDIM;
    const float* Qg = g_q + base + (size_t)qt * 64 * HDIM;
    const float* Kg = g_k + base;
    const float* Vg = g_v + base;

    // Load Q tile (64x64) -> smem as tf32
    #pragma unroll
    for (int i = 0; i < 8; i++) {
        int id = tid + i * 128;
        int r  = id >> 4;
        int cc = (id & 15) << 2;
        float4 v4 = *(const float4*)(Qg + r * HDIM + cc);
        sQ[r * 72 + cc + 0] = __uint_as_float(f2tf(v4.x));
        sQ[r * 72 + cc + 1] = __uint_as_float(f2tf(v4.y));
        sQ[r * 72 + cc + 2] = __uint_as_float(f2tf(v4.z));
        sQ[r * 72 + cc + 3] = __uint_as_float(f2tf(v4.w));
    }
    __syncthreads();

    // Extract Q A-fragments once (per warp, its 16 rows); sQ then becomes P.
    uint32_t qa[8][4];
    const int pr = warp * 16 + g;
    #pragma unroll
    for (int kk = 0; kk < 8; kk++) {
        qa[kk][0] = __float_as_uint(sQ[pr * 72 + kk * 8 + t]);
        qa[kk][1] = __float_as_uint(sQ[(pr + 8) * 72 + kk * 8 + t]);
        qa[kk][2] = __float_as_uint(sQ[pr * 72 + kk * 8 + t + 4]);
        qa[kk][3] = __float_as_uint(sQ[(pr + 8) * 72 + kk * 8 + t + 4]);
    }

    float oc[8][4];
    #pragma unroll
    for (int ni = 0; ni < 8; ni++)
        #pragma unroll
        for (int j = 0; j < 4; j++) oc[ni][j] = 0.0f;

    float m0 = -1e30f, m1 = -1e30f, l0 = 0.0f, l1 = 0.0f;
    const float LOG2E = 1.4426950408889634f;
    const float SCL   = 0.125f;   // 1/sqrt(64)

    for (int kt = 0; kt < SEQ / 64; kt++) {
        __syncthreads();   // prev iteration's K/V consumption complete
        #pragma unroll
        for (int i = 0; i < 8; i++) {
            int id = tid + i * 128;
            int r  = id >> 4;
            int cc = (id & 15) << 2;
            float4 vk = *(const float4*)(Kg + ((size_t)kt * 64 + r) * HDIM + cc);
            float4 vv = *(const float4*)(Vg + ((size_t)kt * 64 + r) * HDIM + cc);
            sK[r * 72 + cc + 0] = __uint_as_float(f2tf(vk.x));
            sK[r * 72 + cc + 1] = __uint_as_float(f2tf(vk.y));
            sK[r * 72 + cc + 2] = __uint_as_float(f2tf(vk.z));
            sK[r * 72 + cc + 3] = __uint_as_float(f2tf(vk.w));
            sV[r * 72 + cc + 0] = __uint_as_float(f2tf(vv.x));
            sV[r * 72 + cc + 1] = __uint_as_float(f2tf(vv.y));
            sV[r * 72 + cc + 2] = __uint_as_float(f2tf(vv.z));
            sV[r * 72 + cc + 3] = __uint_as_float(f2tf(vv.w));
        }
        __syncthreads();

        // S = Q @ K^T (64x64 per CTA; this warp: rows pr.. / 16)
        float sc[8][4];
        #pragma unroll
        for (int ni = 0; ni < 8; ni++)
            #pragma unroll
            for (int j = 0; j < 4; j++) sc[ni][j] = 0.0f;

        #pragma unroll
        for (int kk = 0; kk < 8; kk++) {
            #pragma unroll
            for (int ni = 0; ni < 8; ni++) {
                uint32_t bb[2];
                int rn = ni * 8 + g;
                bb[0] = __float_as_uint(sK[rn * 72 + kk * 8 + t]);
                bb[1] = __float_as_uint(sK[rn * 72 + kk * 8 + t + 4]);
                mma_tf32(sc[ni], qa[kk], bb);
            }
        }

        // online softmax (rows r0 = pr, r1 = pr+8 of this thread)
        #pragma unroll
        for (int ni = 0; ni < 8; ni++)
            #pragma unroll
            for (int j = 0; j < 4; j++) sc[ni][j] *= SCL;

        float mx0 = -1e30f, mx1 = -1e30f;
        #pragma unroll
        for (int ni = 0; ni < 8; ni++) {
            mx0 = fmaxf(mx0, fmaxf(sc[ni][0], sc[ni][1]));
            mx1 = fmaxf(mx1, fmaxf(sc[ni][2], sc[ni][3]));
        }
        mx0 = fmaxf(mx0, __shfl_xor_sync(0xffffffffu, mx0, 1));
        mx0 = fmaxf(mx0, __shfl_xor_sync(0xffffffffu, mx0, 2));
        mx1 = fmaxf(mx1, __shfl_xor_sync(0xffffffffu, mx1, 1));
        mx1 = fmaxf(mx1, __shfl_xor_sync(0xffffffffu, mx1, 2));

        float mn0 = fmaxf(m0, mx0);
        float mn1 = fmaxf(m1, mx1);
        float a0 = exp2f((m0 - mn0) * LOG2E);
        float a1 = exp2f((m1 - mn1) * LOG2E);
        m0 = mn0; m1 = mn1;

        float rs0 = 0.0f, rs1 = 0.0f;
        #pragma unroll
        for (int ni = 0; ni < 8; ni++) {
            sc[ni][0] = exp2f((sc[ni][0] - m0) * LOG2E);
            sc[ni][1] = exp2f((sc[ni][1] - m0) * LOG2E);
            sc[ni][2] = exp2f((sc[ni][2] - m1) * LOG2E);
            sc[ni][3] = exp2f((sc[ni][3] - m1) * LOG2E);
            rs0 += sc[ni][0] + sc[ni][1];
            rs1 += sc[ni][2] + sc[ni][3];
        }
        rs0 += __shfl_xor_sync(0xffffffffu, rs0, 1);
        rs0 += __shfl_xor_sync(0xffffffffu, rs0, 2);
        rs1 += __shfl_xor_sync(0xffffffffu, rs1, 1);
        rs1 += __shfl_xor_sync(0xffffffffu, rs1, 2);
        l0 = l0 * a0 + rs0;
        l1 = l1 * a1 + rs1;

        #pragma unroll
        for (int ni = 0; ni < 8; ni++) {
            oc[ni][0] *= a0; oc[ni][1] *= a0;
            oc[ni][2] *= a1; oc[ni][3] *= a1;
        }

        // store P (warp-private rows of sQ region)
        #pragma unroll
        for (int ni = 0; ni < 8; ni++) {
            int cc = ni * 8 + 2 * t;
            sQ[pr * 72 + cc]           = __uint_as_float(f2tf(sc[ni][0]));
            sQ[pr * 72 + cc + 1]       = __uint_as_float(f2tf(sc[ni][1]));
            sQ[(pr + 8) * 72 + cc]     = __uint_as_float(f2tf(sc[ni][2]));
            sQ[(pr + 8) * 72 + cc + 1] = __uint_as_float(f2tf(sc[ni][3]));
        }
        __syncwarp();

        // O += P @ V
        #pragma unroll
        for (int kk = 0; kk < 8; kk++) {
            uint32_t pa[4];
            pa[0] = __float_as_uint(sQ[pr * 72 + kk * 8 + t]);
            pa[1] = __float_as_uint(sQ[(pr + 8) * 72 + kk * 8 + t]);
            pa[2] = __float_as_uint(sQ[pr * 72 + kk * 8 + t + 4]);
            pa[3] = __float_as_uint(sQ[(pr + 8) * 72 + kk * 8 + t + 4]);
            #pragma unroll
            for (int ni = 0; ni < 8; ni++) {
                uint32_t bb[2];
                bb[0] = __float_as_uint(sV[(kk * 8 + t) * 72 + ni * 8 + g]);
                bb[1] = __float_as_uint(sV[(kk * 8 + t + 4) * 72 + ni * 8 + g]);
                mma_tf32(oc[ni], pa, bb);
            }
        }
    }

    // epilogue: normalize and write to g_att as [B, S, H*hd]
    float i0 = 1.0f / l0;
    float i1 = 1.0f / l1;
    int r0 = qt * 64 + warp * 16 + g;
    float* Og = g_att + (size_t)b * SEQ * EDIM + (size_t)h * HDIM;
    #pragma unroll
    for (int ni = 0; ni < 8; ni++) {
        int cc = ni * 8 + 2 * t;
        Og[(size_t)r0 * EDIM + cc]           = oc[ni][0] * i0;
        Og[(size_t)r0 * EDIM + cc + 1]       = oc[ni][1] * i0;
        Og[(size_t)(r0 + 8) * EDIM + cc]     = oc[ni][2] * i1;
        Og[(size_t)(r0 + 8) * EDIM + cc + 1] = oc[ni][3] * i1;
    }
}

extern "C" void kernel_launch(void* const* d_in, const int* in_sizes, int n_in,
                              void* d_out, int out_size)
{
    const float* x     = (const float*)d_in[0];
    const float* hmask = (const float*)d_in[1];
    const float* qkv_w = (const float*)d_in[2];
    const float* qkv_b = (const float*)d_in[3];
    const float* fc_w  = (const float*)d_in[4];
    const float* fc_b  = (const float*)d_in[5];
    float* out = (float*)d_out;

    // 1) QKV projection + bias + head_mask + scatter to [B,H,S,hd]
    gemm_tf32_kernel<1><<<dim3(3 * EDIM / 128, BATCH * SEQ / 128), 256>>>(
        x, qkv_w, qkv_b, hmask, nullptr, BATCH * SEQ, 3 * EDIM, EDIM);

    // 2) flash attention -> g_att [B,S,D]
    const int fa_smem = 3 * 64 * 72 * (int)sizeof(float);   // 55296 B
    cudaFuncSetAttribute(flash_attn_kernel,
                         cudaFuncAttributeMaxDynamicSharedMemorySize, fa_smem);
    flash_attn_kernel<<<dim3(SEQ / 64, NHEAD, BATCH), 128, fa_smem>>>();

    // 3) output projection + bias -> d_out
    gemm_tf32_kernel<0><<<dim3(EDIM / 128, BATCH * SEQ / 128), 256>>>(
        nullptr, fc_w, fc_b, nullptr, out, BATCH * SEQ, EDIM, EDIM);
}